// round 14
// baseline (speedup 1.0000x reference)
#include <cuda_runtime.h>
#include <cuda_fp16.h>
#include <cuda_bf16.h>
#include <cstdint>

// Shapes (fixed)
#define BSZ  8
#define CIN  512
#define COUT 512
#define SSZ  512
#define HDIM 64
#define WDIM 64

// padded x: [b][pr 0..65][pc 0..65][ci], ci contiguous
#define XH 66
#define XW 66

// GEMM tiling: block M128 x N256, 8 warps (2m x 4n), per-warp m64 x n64
#define MT 128
#define NT 256
#define KC 64           // ci per k-iter (64 fp16 = 128B row)
#define NITER 72        // 9 taps * 8 ci-chunks (single fp16 term)

// smem: 3 stages * (A 16KB + B 32KB) = 144KB; epilogue D[256n][132m] f32 reuses it
#define NSTG 3
#define STGB 49152
#define SMEM_BYTES (NSTG * STGB + 1024)

// ---- device scratch (allocation-free) ----
__device__ float g_s[BSZ * CIN];
__device__ float g_g[BSZ * COUT];
__device__ float g_wsq[COUT * CIN];
__device__ __half g_xh[(size_t)BSZ * XH * XW * CIN];   // modulated x, fp16
__device__ __half g_w[9 * COUT * CIN];                 // [tap][co][ci], fp16

static __device__ __forceinline__ float warp_sum(float v) {
    #pragma unroll
    for (int o = 16; o; o >>= 1) v += __shfl_xor_sync(0xffffffffu, v, o);
    return v;
}

// ---- PTX helpers (arch-generic only) ----
static __device__ __forceinline__ unsigned smem_u32(const void* p) {
    return (unsigned)__cvta_generic_to_shared(p);
}
static __device__ __forceinline__ void cp16(unsigned dst, const void* src) {
    asm volatile("cp.async.cg.shared.global [%0], [%1], 16;" :: "r"(dst), "l"(src));
}
static __device__ __forceinline__ void cp_commit() {
    asm volatile("cp.async.commit_group;");
}
static __device__ __forceinline__ void cp_wait1() {
    asm volatile("cp.async.wait_group 1;");
}
static __device__ __forceinline__ void ldm_x4(unsigned& r0, unsigned& r1,
                                              unsigned& r2, unsigned& r3, unsigned a) {
    asm volatile("ldmatrix.sync.aligned.m8n8.x4.shared.b16 {%0,%1,%2,%3}, [%4];"
                 : "=r"(r0), "=r"(r1), "=r"(r2), "=r"(r3) : "r"(a));
}
static __device__ __forceinline__ void mma16816(float* c, const unsigned* a, const unsigned* b) {
    asm volatile(
        "mma.sync.aligned.m16n8k16.row.col.f32.f16.f16.f32 "
        "{%0,%1,%2,%3}, {%4,%5,%6,%7}, {%8,%9}, {%0,%1,%2,%3};"
        : "+f"(c[0]), "+f"(c[1]), "+f"(c[2]), "+f"(c[3])
        : "r"(a[0]), "r"(a[1]), "r"(a[2]), "r"(a[3]), "r"(b[0]), "r"(b[1]));
}

#define SWZ(o) ((o) ^ (((o) >> 3) & 0x70))

// ================= prep kernels =================

// fused: blocks [0,512) do style GEMV; blocks [512,1536) do weight fp16 conversion + wsq
__global__ void k_prep0(const float* __restrict__ style,
                        const float* __restrict__ mod_weight,
                        const float* __restrict__ mod_bias,
                        const float* __restrict__ weight,
                        float* __restrict__ out_tail) {
    int tid = threadIdx.x;
    if (blockIdx.x < 512) {
        int warp = (blockIdx.x * 256 + tid) >> 5;   // 0..4095 = b*512+ci
        int lane = tid & 31;
        int b = warp >> 9, ci = warp & 511;
        const float* st = style + (size_t)b * SSZ;
        const float* mw = mod_weight + (size_t)ci * SSZ;
        float acc = 0.f;
        for (int t = lane; t < SSZ; t += 32) acc += st[t] * mw[t];
        acc = warp_sum(acc);
        if (lane == 0) {
            const float lin_scale = 0.044194173824159216f;  // 1/sqrt(512)
            float v = acc * lin_scale + mod_bias[ci];
            g_s[warp] = v;
            if (out_tail) out_tail[warp] = v;
        }
    } else {
        int idx = (blockIdx.x - 512) * 256 + tid;   // 0..262143 = co*512+ci
        int co = idx >> 9, ci = idx & 511;
        const float* wp = weight + (size_t)idx * 9;
        float sq = 0.f;
        #pragma unroll
        for (int k = 0; k < 9; ++k) {
            float v = wp[k];
            sq += v * v;
            g_w[(size_t)k * (COUT * CIN) + (size_t)co * CIN + ci] = __float2half_rn(v);
        }
        g_wsq[(size_t)co * CIN + ci] = sq;
    }
}

__global__ void k_demod() {
    int warp = (blockIdx.x * blockDim.x + threadIdx.x) >> 5;
    int lane = threadIdx.x & 31;
    if (warp >= BSZ * COUT) return;
    int b = warp >> 9, co = warp & 511;
    const float* sp = g_s + (size_t)b * CIN;
    const float* wq = g_wsq + (size_t)co * CIN;
    float acc = 0.f;
    for (int t = lane; t < CIN; t += 32) {
        float sv = sp[t];
        acc += sv * sv * wq[t];
    }
    acc = warp_sum(acc);
    if (lane == 0) {
        const float cs = 0.014731391274719742f;  // 1/sqrt(512*9)
        g_g[warp] = cs * rsqrtf(cs * cs * acc + 1e-8f);
    }
}

// x -> padded, modulated fp16 (with fused halo zeroing). Block = (b, h row).
__global__ void k_xprep(const float* __restrict__ x) {
    __shared__ float sx[128][65];
    int b = blockIdx.x >> 6;
    int h = blockIdx.x & 63;
    int tid = threadIdx.x;

    {
        unsigned* c0 = (unsigned*)(g_xh + (((size_t)b * XH + h + 1) * XW + 0) * CIN);
        unsigned* c1 = (unsigned*)(g_xh + (((size_t)b * XH + h + 1) * XW + 65) * CIN);
        c0[tid] = 0u;
        c1[tid] = 0u;
    }
    if (h == 0) {
        uint4* p = (uint4*)(g_xh + ((size_t)b * XH + 0) * XW * CIN);
        for (int i = tid; i < (XW * CIN) / 8; i += 256) p[i] = make_uint4(0, 0, 0, 0);
    }
    if (h == 63) {
        uint4* p = (uint4*)(g_xh + ((size_t)b * XH + 65) * XW * CIN);
        for (int i = tid; i < (XW * CIN) / 8; i += 256) p[i] = make_uint4(0, 0, 0, 0);
    }

    for (int cb = 0; cb < 4; ++cb) {
        int cbase = cb * 128;
        __syncthreads();
        {
            int w = tid & 63;
            int cl = tid >> 6;
            for (int k = 0; k < 32; ++k) {
                int ci = cl + k * 4;
                sx[ci][w] = x[(((size_t)b * CIN + cbase + ci) * HDIM + h) * WDIM + w];
            }
        }
        __syncthreads();
        for (int k = 0; k < 16; ++k) {
            int idx = tid + k * 256;
            int w = idx >> 6;
            int cp = idx & 63;
            int ci = cp * 2;
            float s0 = g_s[b * CIN + cbase + ci];
            float s1 = g_s[b * CIN + cbase + ci + 1];
            __half2 hv = __floats2half2_rn(sx[ci][w] * s0, sx[ci + 1][w] * s1);
            *(__half2*)(g_xh + (((size_t)b * XH + h + 1) * XW + (w + 1)) * CIN
                        + cbase + ci) = hv;
        }
    }
}

// ================= main conv: mma.sync fp16 implicit GEMM, m64n64 warp tile ==
__global__ __launch_bounds__(256, 1)
void k_conv(float* __restrict__ out) {
    extern __shared__ char dyn_smem[];
    const unsigned sbase = (smem_u32(dyn_smem) + 1023u) & ~1023u;

    const int tid = threadIdx.x;
    const int wid = tid >> 5;
    const int lane = tid & 31;
    const int warp_m = wid & 1;       // m64 slice
    const int warp_n = wid >> 1;      // n64 slice (0..3)
    const int b   = blockIdx.z;
    const int co0 = blockIdx.y * NT;
    const int gr0 = (int)(blockIdx.x >> 3) * 16;
    const int gc0 = (int)(blockIdx.x & 7) * 8;

    float acc[4][8][4];
    #pragma unroll
    for (int mt = 0; mt < 4; ++mt)
        #pragma unroll
        for (int nt = 0; nt < 8; ++nt)
            #pragma unroll
            for (int r = 0; r < 4; ++r) acc[mt][nt][r] = 0.f;

    // ---- cp.async per-thread constants: A 1024 chunks (4/thr), B 2048 (8/thr) ----
    unsigned dstA[4], srcA[4];
    unsigned dstB[8], srcB[8];
    #pragma unroll
    for (int t = 0; t < 4; ++t) {
        int idx = tid + t * 256;               // 0..1023
        dstA[t] = SWZ((unsigned)idx * 16u);
        int m = idx >> 3, q = idx & 7;
        srcA[t] = (unsigned)(((gr0 + (m >> 3)) * XW + gc0 + (m & 7)) * (CIN * 2)) + q * 16;
    }
    #pragma unroll
    for (int t = 0; t < 8; ++t) {
        int idx = tid + t * 256;               // 0..2047
        dstB[t] = SWZ((unsigned)idx * 16u);
        int n = idx >> 3, q = idx & 7;
        srcB[t] = (unsigned)(n * (CIN * 2)) + q * 16;
    }
    const size_t bxoff = (size_t)b * XH * XW * (CIN * 2);

    auto iter_bases = [&](int s, const char*& uA, const char*& uB) {
        int tap = s >> 3;
        int kc = s & 7;
        int dr = tap / 3, dc = tap - dr * 3;
        uA = (const char*)g_xh + bxoff + (size_t)((dr * XW + dc) * (CIN * 2)) + kc * (KC * 2);
        uB = (const char*)g_w + (size_t)tap * (COUT * CIN * 2)
             + (size_t)co0 * (CIN * 2) + kc * (KC * 2);
    };

    auto issue_copies = [&](int stage, int s) {
        const char *uA, *uB;
        iter_bases(s, uA, uB);
        unsigned sa = sbase + stage * STGB;
        unsigned sb = sa + 16384;
        #pragma unroll
        for (int t = 0; t < 4; ++t) cp16(sa + dstA[t], uA + srcA[t]);
        #pragma unroll
        for (int t = 0; t < 8; ++t) cp16(sb + dstB[t], uB + srcB[t]);
        cp_commit();
    };

    // ---- ldmatrix per-thread address components ----
    int a_row[4];
    #pragma unroll
    for (int mt = 0; mt < 4; ++mt) a_row[mt] = warp_m * 64 + mt * 16 + (lane & 15);
    const int a_csel = lane >> 4;                     // 0/1
    int b_row[4];
    #pragma unroll
    for (int q = 0; q < 4; ++q)
        b_row[q] = warp_n * 64 + q * 16 + (((lane >> 4) & 1) << 3) + (lane & 7);
    const int b_csel = (lane >> 3) & 1;

    // prologue: iters 0,1 into stages 0,1
    issue_copies(0, 0);
    issue_copies(1, 1);

    for (int s = 0; s < NITER; ++s) {
        const int st = s % NSTG;
        cp_wait1();
        __syncthreads();

        if (s + 2 < NITER) issue_copies((s + 2) % NSTG, s + 2);
        else cp_commit();

        const unsigned sa = sbase + st * STGB;
        const unsigned sb = sa + 16384;

        #pragma unroll
        for (int ks = 0; ks < 4; ++ks) {
            unsigned af[4][4];
            #pragma unroll
            for (int mt = 0; mt < 4; ++mt) {
                int row = a_row[mt];
                unsigned addr = sa + row * 128 + (((2 * ks + a_csel) ^ (row & 7)) << 4);
                ldm_x4(af[mt][0], af[mt][1], af[mt][2], af[mt][3], addr);
            }
            unsigned bf[8][2];
            #pragma unroll
            for (int q = 0; q < 4; ++q) {
                int row = b_row[q];
                unsigned addr = sb + row * 128 + (((2 * ks + b_csel) ^ (row & 7)) << 4);
                unsigned r0, r1, r2, r3;
                ldm_x4(r0, r1, r2, r3, addr);
                bf[2 * q][0] = r0;  bf[2 * q][1] = r1;
                bf[2 * q + 1][0] = r2;  bf[2 * q + 1][1] = r3;
            }
            #pragma unroll
            for (int mt = 0; mt < 4; ++mt)
                #pragma unroll
                for (int nt = 0; nt < 8; ++nt)
                    mma16816(acc[mt][nt], af[mt], bf[nt]);
        }
    }

    // ================= epilogue: smem transpose -> coalesced demod store =====
    __syncthreads();
    float* smemD = (float*)(dyn_smem + ((1024 - (smem_u32(dyn_smem) & 1023)) & 1023));
    float* gsm = smemD + 256 * 132;
    gsm[tid] = g_g[b * COUT + co0 + tid];
    #pragma unroll
    for (int mt = 0; mt < 4; ++mt)
        #pragma unroll
        for (int nt = 0; nt < 8; ++nt) {
            int n = warp_n * 64 + nt * 8 + (lane & 3) * 2;
            int m = warp_m * 64 + mt * 16 + (lane >> 2);
            smemD[n * 132 + m]             = acc[mt][nt][0];
            smemD[(n + 1) * 132 + m]       = acc[mt][nt][1];
            smemD[n * 132 + m + 8]         = acc[mt][nt][2];
            smemD[(n + 1) * 132 + m + 8]   = acc[mt][nt][3];
        }
    __syncthreads();

    #pragma unroll 4
    for (int it = 0; it < 128; ++it) {
        int idx = tid + it * 256;       // 0..32767
        int n = idx >> 7;
        int m = idx & 127;
        int co = co0 + n;
        int h = gr0 + (m >> 3);
        int w = gc0 + (m & 7);
        out[(((size_t)b * COUT + co) * HDIM + h) * WDIM + w] = smemD[n * 132 + m] * gsm[n];
    }
}

extern "C" void kernel_launch(void* const* d_in, const int* in_sizes, int n_in,
                              void* d_out, int out_size) {
    const float* x          = (const float*)d_in[0];
    const float* style      = (const float*)d_in[1];
    const float* weight     = (const float*)d_in[2];
    const float* mod_weight = (const float*)d_in[3];
    const float* mod_bias   = (const float*)d_in[4];
    float* out = (float*)d_out;

    const long long conv_elems = (long long)BSZ * COUT * HDIM * WDIM;
    float* tail = (out_size >= conv_elems + BSZ * CIN) ? (out + conv_elems) : nullptr;

    cudaFuncSetAttribute(k_conv, cudaFuncAttributeMaxDynamicSharedMemorySize, SMEM_BYTES);

    k_prep0<<<1536, 256>>>(style, mod_weight, mod_bias, weight, tail);
    k_demod<<<(BSZ * COUT * 32) / 256, 256>>>();
    k_xprep<<<BSZ * HDIM, 256>>>(x);

    dim3 grid(32, NT == 256 ? 2 : 4, BSZ);   // (32, 2, 8)
    k_conv<<<grid, 256, SMEM_BYTES>>>(out);
}

// round 16
// speedup vs baseline: 1.0488x; 1.0488x over previous
#include <cuda_runtime.h>
#include <cuda_fp16.h>
#include <cuda_bf16.h>
#include <cstdint>

// Shapes (fixed)
#define BSZ  8
#define CIN  512
#define COUT 512
#define SSZ  512
#define HDIM 64
#define WDIM 64

// padded x: [b][pr 0..65][pc 0..65][ci], ci contiguous
#define XH 66
#define XW 66

// GEMM tiling: block M128 x N256, 8 warps (2m x 4n), per-warp m64 x n64
#define MT 128
#define NT 256
#define KC 64           // ci per k-iter (64 fp16 = 128B row)
#define NITER 72        // 9 taps * 8 ci-chunks (single fp16 term)

// smem: 4 stages * (A 16KB + B 32KB) = 192KB; epilogue D[256n][132m] f32 reuses it
#define NSTG 4
#define STGB 49152
#define SMEM_BYTES (NSTG * STGB + 1024)

// ---- device scratch (allocation-free) ----
__device__ float g_s[BSZ * CIN];
__device__ float g_g[BSZ * COUT];
__device__ float g_wsq[COUT * CIN];
__device__ __half g_xh[(size_t)BSZ * XH * XW * CIN];   // modulated x, fp16
__device__ __half g_w[9 * COUT * CIN];                 // [tap][co][ci], fp16

static __device__ __forceinline__ float warp_sum(float v) {
    #pragma unroll
    for (int o = 16; o; o >>= 1) v += __shfl_xor_sync(0xffffffffu, v, o);
    return v;
}

// ---- PTX helpers (arch-generic only) ----
static __device__ __forceinline__ unsigned smem_u32(const void* p) {
    return (unsigned)__cvta_generic_to_shared(p);
}
static __device__ __forceinline__ void cp16(unsigned dst, const void* src) {
    asm volatile("cp.async.cg.shared.global [%0], [%1], 16;" :: "r"(dst), "l"(src));
}
static __device__ __forceinline__ void cp_commit() {
    asm volatile("cp.async.commit_group;");
}
static __device__ __forceinline__ void cp_wait1() {
    asm volatile("cp.async.wait_group 1;");
}
static __device__ __forceinline__ void ldm_x4(unsigned& r0, unsigned& r1,
                                              unsigned& r2, unsigned& r3, unsigned a) {
    asm volatile("ldmatrix.sync.aligned.m8n8.x4.shared.b16 {%0,%1,%2,%3}, [%4];"
                 : "=r"(r0), "=r"(r1), "=r"(r2), "=r"(r3) : "r"(a));
}
static __device__ __forceinline__ void mma16816(float* c, const unsigned* a, const unsigned* b) {
    asm volatile(
        "mma.sync.aligned.m16n8k16.row.col.f32.f16.f16.f32 "
        "{%0,%1,%2,%3}, {%4,%5,%6,%7}, {%8,%9}, {%0,%1,%2,%3};"
        : "+f"(c[0]), "+f"(c[1]), "+f"(c[2]), "+f"(c[3])
        : "r"(a[0]), "r"(a[1]), "r"(a[2]), "r"(a[3]), "r"(b[0]), "r"(b[1]));
}

#define SWZ(o) ((o) ^ (((o) >> 3) & 0x70))

// ================= prep kernels =================

// fused: blocks [0,512) do style GEMV; blocks [512,1536) do weight fp16 conversion + wsq
__global__ void k_prep0(const float* __restrict__ style,
                        const float* __restrict__ mod_weight,
                        const float* __restrict__ mod_bias,
                        const float* __restrict__ weight,
                        float* __restrict__ out_tail) {
    int tid = threadIdx.x;
    if (blockIdx.x < 512) {
        int warp = (blockIdx.x * 256 + tid) >> 5;   // 0..4095 = b*512+ci
        int lane = tid & 31;
        int b = warp >> 9, ci = warp & 511;
        const float* st = style + (size_t)b * SSZ;
        const float* mw = mod_weight + (size_t)ci * SSZ;
        float acc = 0.f;
        for (int t = lane; t < SSZ; t += 32) acc += st[t] * mw[t];
        acc = warp_sum(acc);
        if (lane == 0) {
            const float lin_scale = 0.044194173824159216f;  // 1/sqrt(512)
            float v = acc * lin_scale + mod_bias[ci];
            g_s[warp] = v;
            if (out_tail) out_tail[warp] = v;
        }
    } else {
        int idx = (blockIdx.x - 512) * 256 + tid;   // 0..262143 = co*512+ci
        int co = idx >> 9, ci = idx & 511;
        const float* wp = weight + (size_t)idx * 9;
        float sq = 0.f;
        #pragma unroll
        for (int k = 0; k < 9; ++k) {
            float v = wp[k];
            sq += v * v;
            g_w[(size_t)k * (COUT * CIN) + (size_t)co * CIN + ci] = __float2half_rn(v);
        }
        g_wsq[(size_t)co * CIN + ci] = sq;
    }
}

__global__ void k_demod() {
    int warp = (blockIdx.x * blockDim.x + threadIdx.x) >> 5;
    int lane = threadIdx.x & 31;
    if (warp >= BSZ * COUT) return;
    int b = warp >> 9, co = warp & 511;
    const float* sp = g_s + (size_t)b * CIN;
    const float* wq = g_wsq + (size_t)co * CIN;
    float acc = 0.f;
    for (int t = lane; t < CIN; t += 32) {
        float sv = sp[t];
        acc += sv * sv * wq[t];
    }
    acc = warp_sum(acc);
    if (lane == 0) {
        const float cs = 0.014731391274719742f;  // 1/sqrt(512*9)
        g_g[warp] = cs * rsqrtf(cs * cs * acc + 1e-8f);
    }
}

// x -> padded, modulated fp16 (with fused halo zeroing). Block = (b, h row).
__global__ void k_xprep(const float* __restrict__ x) {
    __shared__ float sx[128][65];
    int b = blockIdx.x >> 6;
    int h = blockIdx.x & 63;
    int tid = threadIdx.x;

    {
        unsigned* c0 = (unsigned*)(g_xh + (((size_t)b * XH + h + 1) * XW + 0) * CIN);
        unsigned* c1 = (unsigned*)(g_xh + (((size_t)b * XH + h + 1) * XW + 65) * CIN);
        c0[tid] = 0u;
        c1[tid] = 0u;
    }
    if (h == 0) {
        uint4* p = (uint4*)(g_xh + ((size_t)b * XH + 0) * XW * CIN);
        for (int i = tid; i < (XW * CIN) / 8; i += 256) p[i] = make_uint4(0, 0, 0, 0);
    }
    if (h == 63) {
        uint4* p = (uint4*)(g_xh + ((size_t)b * XH + 65) * XW * CIN);
        for (int i = tid; i < (XW * CIN) / 8; i += 256) p[i] = make_uint4(0, 0, 0, 0);
    }

    for (int cb = 0; cb < 4; ++cb) {
        int cbase = cb * 128;
        __syncthreads();
        {
            int w = tid & 63;
            int cl = tid >> 6;
            for (int k = 0; k < 32; ++k) {
                int ci = cl + k * 4;
                sx[ci][w] = x[(((size_t)b * CIN + cbase + ci) * HDIM + h) * WDIM + w];
            }
        }
        __syncthreads();
        for (int k = 0; k < 16; ++k) {
            int idx = tid + k * 256;
            int w = idx >> 6;
            int cp = idx & 63;
            int ci = cp * 2;
            float s0 = g_s[b * CIN + cbase + ci];
            float s1 = g_s[b * CIN + cbase + ci + 1];
            __half2 hv = __floats2half2_rn(sx[ci][w] * s0, sx[ci + 1][w] * s1);
            *(__half2*)(g_xh + (((size_t)b * XH + h + 1) * XW + (w + 1)) * CIN
                        + cbase + ci) = hv;
        }
    }
}

// ========== main conv: mma.sync fp16, m64n64 warp tile, 4-stage pipeline =====
__global__ __launch_bounds__(256, 1)
void k_conv(float* __restrict__ out) {
    extern __shared__ char dyn_smem[];
    const unsigned sbase = (smem_u32(dyn_smem) + 1023u) & ~1023u;

    const int tid = threadIdx.x;
    const int wid = tid >> 5;
    const int lane = tid & 31;
    const int warp_m = wid & 1;       // m64 slice
    const int warp_n = wid >> 1;      // n64 slice (0..3)
    const int b   = blockIdx.z;
    const int co0 = blockIdx.y * NT;
    const int gr0 = (int)(blockIdx.x >> 3) * 16;
    const int gc0 = (int)(blockIdx.x & 7) * 8;

    float acc[4][8][4];
    #pragma unroll
    for (int mt = 0; mt < 4; ++mt)
        #pragma unroll
        for (int nt = 0; nt < 8; ++nt)
            #pragma unroll
            for (int r = 0; r < 4; ++r) acc[mt][nt][r] = 0.f;

    // ---- cp.async per-thread constants: A 1024 chunks (4/thr), B 2048 (8/thr) ----
    unsigned dstA[4], srcA[4];
    unsigned dstB[8], srcB[8];
    #pragma unroll
    for (int t = 0; t < 4; ++t) {
        int idx = tid + t * 256;               // 0..1023
        dstA[t] = SWZ((unsigned)idx * 16u);
        int m = idx >> 3, q = idx & 7;
        srcA[t] = (unsigned)(((gr0 + (m >> 3)) * XW + gc0 + (m & 7)) * (CIN * 2)) + q * 16;
    }
    #pragma unroll
    for (int t = 0; t < 8; ++t) {
        int idx = tid + t * 256;               // 0..2047
        dstB[t] = SWZ((unsigned)idx * 16u);
        int n = idx >> 3, q = idx & 7;
        srcB[t] = (unsigned)(n * (CIN * 2)) + q * 16;
    }
    const size_t bxoff = (size_t)b * XH * XW * (CIN * 2);

    auto iter_bases = [&](int s, const char*& uA, const char*& uB) {
        int tap = s >> 3;
        int kc = s & 7;
        int dr = tap / 3, dc = tap - dr * 3;
        uA = (const char*)g_xh + bxoff + (size_t)((dr * XW + dc) * (CIN * 2)) + kc * (KC * 2);
        uB = (const char*)g_w + (size_t)tap * (COUT * CIN * 2)
             + (size_t)co0 * (CIN * 2) + kc * (KC * 2);
    };

    auto issue_copies = [&](int stage, int s) {
        const char *uA, *uB;
        iter_bases(s, uA, uB);
        unsigned sa = sbase + stage * STGB;
        unsigned sb = sa + 16384;
        #pragma unroll
        for (int t = 0; t < 4; ++t) cp16(sa + dstA[t], uA + srcA[t]);
        #pragma unroll
        for (int t = 0; t < 8; ++t) cp16(sb + dstB[t], uB + srcB[t]);
        cp_commit();
    };

    // ---- ldmatrix per-thread address components ----
    int a_row[4];
    #pragma unroll
    for (int mt = 0; mt < 4; ++mt) a_row[mt] = warp_m * 64 + mt * 16 + (lane & 15);
    const int a_csel = lane >> 4;                     // 0/1
    int b_row[4];
    #pragma unroll
    for (int q = 0; q < 4; ++q)
        b_row[q] = warp_n * 64 + q * 16 + (((lane >> 4) & 1) << 3) + (lane & 7);
    const int b_csel = (lane >> 3) & 1;

    // prologue: iters 0,1 into stages 0,1
    issue_copies(0, 0);
    issue_copies(1, 1);

    for (int s = 0; s < NITER; ++s) {
        const int st = s & 3;          // NSTG=4
        cp_wait1();
        // 4-deep ring: stage (s+2)%4 was last read at iter s-2, so a barrier
        // every OTHER iteration suffices (sync at even s covers reads < s).
        if ((s & 1) == 0) __syncthreads();

        if (s + 2 < NITER) issue_copies((s + 2) & 3, s + 2);
        else cp_commit();

        const unsigned sa = sbase + st * STGB;
        const unsigned sb = sa + 16384;

        #pragma unroll
        for (int ks = 0; ks < 4; ++ks) {
            unsigned af[4][4];
            #pragma unroll
            for (int mt = 0; mt < 4; ++mt) {
                int row = a_row[mt];
                unsigned addr = sa + row * 128 + (((2 * ks + a_csel) ^ (row & 7)) << 4);
                ldm_x4(af[mt][0], af[mt][1], af[mt][2], af[mt][3], addr);
            }
            unsigned bf[8][2];
            #pragma unroll
            for (int q = 0; q < 4; ++q) {
                int row = b_row[q];
                unsigned addr = sb + row * 128 + (((2 * ks + b_csel) ^ (row & 7)) << 4);
                unsigned r0, r1, r2, r3;
                ldm_x4(r0, r1, r2, r3, addr);
                bf[2 * q][0] = r0;  bf[2 * q][1] = r1;
                bf[2 * q + 1][0] = r2;  bf[2 * q + 1][1] = r3;
            }
            #pragma unroll
            for (int mt = 0; mt < 4; ++mt)
                #pragma unroll
                for (int nt = 0; nt < 8; ++nt)
                    mma16816(acc[mt][nt], af[mt], bf[nt]);
        }
    }

    // ================= epilogue: smem transpose -> coalesced demod store =====
    __syncthreads();
    float* smemD = (float*)(dyn_smem + ((1024 - (smem_u32(dyn_smem) & 1023)) & 1023));
    float* gsm = smemD + 256 * 132;
    gsm[tid] = g_g[b * COUT + co0 + tid];
    #pragma unroll
    for (int mt = 0; mt < 4; ++mt)
        #pragma unroll
        for (int nt = 0; nt < 8; ++nt) {
            int n = warp_n * 64 + nt * 8 + (lane & 3) * 2;
            int m = warp_m * 64 + mt * 16 + (lane >> 2);
            smemD[n * 132 + m]             = acc[mt][nt][0];
            smemD[(n + 1) * 132 + m]       = acc[mt][nt][1];
            smemD[n * 132 + m + 8]         = acc[mt][nt][2];
            smemD[(n + 1) * 132 + m + 8]   = acc[mt][nt][3];
        }
    __syncthreads();

    #pragma unroll 4
    for (int it = 0; it < 128; ++it) {
        int idx = tid + it * 256;       // 0..32767
        int n = idx >> 7;
        int m = idx & 127;
        int co = co0 + n;
        int h = gr0 + (m >> 3);
        int w = gc0 + (m & 7);
        out[(((size_t)b * COUT + co) * HDIM + h) * WDIM + w] = smemD[n * 132 + m] * gsm[n];
    }
}

extern "C" void kernel_launch(void* const* d_in, const int* in_sizes, int n_in,
                              void* d_out, int out_size) {
    const float* x          = (const float*)d_in[0];
    const float* style      = (const float*)d_in[1];
    const float* weight     = (const float*)d_in[2];
    const float* mod_weight = (const float*)d_in[3];
    const float* mod_bias   = (const float*)d_in[4];
    float* out = (float*)d_out;

    const long long conv_elems = (long long)BSZ * COUT * HDIM * WDIM;
    float* tail = (out_size >= conv_elems + BSZ * CIN) ? (out + conv_elems) : nullptr;

    cudaFuncSetAttribute(k_conv, cudaFuncAttributeMaxDynamicSharedMemorySize, SMEM_BYTES);

    k_prep0<<<1536, 256>>>(style, mod_weight, mod_bias, weight, tail);
    k_demod<<<(BSZ * COUT * 32) / 256, 256>>>();
    k_xprep<<<BSZ * HDIM, 256>>>(x);

    dim3 grid(32, 2, BSZ);   // (32, 2, 8)
    k_conv<<<grid, 256, SMEM_BYTES>>>(out);
}